// round 9
// baseline (speedup 1.0000x reference)
#include <cuda_runtime.h>
#include <cuda_fp16.h>
#include <cuda_bf16.h>

// Problem constants (match reference)
#define NN   100000      // nodes
#define FIN  128         // input features
#define HID  64          // hidden
#define NCLS 40          // classes
#define NE   1600000     // edges

#define SCAN_B 1024
#define NB ((NN + SCAN_B - 1) / SCAN_B)   // 98
#define GEMM1_BLOCKS ((NN + 127) / 128)   // 782
#define CNT_BLOCKS 1024
#define BUCKET_BLOCKS ((NE + 255) / 256)          // 6250
#define SCALE_BLOCKS ((NN * 8 + 255) / 256)       // 3125

// Scratch (device globals — no allocation allowed)
__device__ int   g_is64;
__device__ int   g_cnt [NN];
__device__ int   g_off [NN + 1];
__device__ int   g_pos [NN];
__device__ int   g_bsum[NB];
__device__ int   g_esrc[NE];          // src indices bucketed by dst (CSR)
__device__ float g_dinv[NN];
__device__ uint4 g_hs1h[NN * 8];      // x@W1 fp16 (unscaled, then scaled in place)
__device__ float g_acc1[NN * HID];    // layer-1 aggregate (fp32, linear reads)
__device__ uint4 g_hs2h[NN * 5];      // (relu@W2)*dinv fp16: 40 halfs/row

// ---------------------------------------------------------------------------
// Packed f32x2 helpers (Blackwell FFMA2 — only reachable via PTX)
__device__ __forceinline__ unsigned long long pk2(float lo, float hi) {
    unsigned long long r;
    asm("mov.b64 %0, {%1, %2};" : "=l"(r) : "f"(lo), "f"(hi));
    return r;
}
__device__ __forceinline__ void fma2(unsigned long long& d,
                                     unsigned long long a, unsigned long long b) {
    asm("fma.rn.f32x2 %0, %1, %2, %0;" : "+l"(d) : "l"(a), "l"(b));
}
__device__ __forceinline__ void unpk2(unsigned long long v, float& x, float& y) {
    asm("mov.b64 {%0, %1}, %2;" : "=f"(x), "=f"(y) : "l"(v));
}

// ---------------------------------------------------------------------------
// Edge-index dtype detection (JAX silently downcasts int64 -> int32 by default)
__device__ __forceinline__ int edge_src(const void* __restrict__ ei, int e) {
    if (g_is64) return (int)((const long long*)ei)[e];
    return ((const int*)ei)[e];
}
__device__ __forceinline__ int edge_dst(const void* __restrict__ ei, int e) {
    if (g_is64) return (int)((const long long*)ei)[NE + e];
    return ((const int*)ei)[NE + e];
}

// Fused: detect dtype (block 0, thread 0) + zero g_cnt (all threads)
__global__ void k_init(const void* __restrict__ ei) {
    if (blockIdx.x == 0 && threadIdx.x == 0) {
        const unsigned long long* p = (const unsigned long long*)ei;
        int is64 = 1;
        for (int i = 0; i < 2048; i++) {
            if (p[i] >= (unsigned long long)NN) { is64 = 0; break; }
        }
        g_is64 = is64;
    }
    int i = blockIdx.x * blockDim.x + threadIdx.x;
    if (i < NN) g_cnt[i] = 0;
}

// ---------------------------------------------------------------------------
// FUSED: GEMM1 (blocks [0, GEMM1_BLOCKS)) + degree count (remaining blocks).
// GEMM1: hs1 = x @ W1 (UNSCALED) fp16. dinv applied in the bucket-phase
// scale role, so GEMM1 has no dependency on the CSR/scan chain.
__global__ void k_gemm1_cnt(const float* __restrict__ x,
                            const float* __restrict__ W1,
                            const void* __restrict__ ei) {
    __shared__ ulonglong2 Ws[FIN * HID / 4];  // 2048 entries = 32KB

    if (blockIdx.x >= GEMM1_BLOCKS) {
        // --- degree count role ---
        int t = (blockIdx.x - GEMM1_BLOCKS) * blockDim.x + threadIdx.x;
        int stride = CNT_BLOCKS * blockDim.x;
        for (int e = t; e < NE; e += stride)
            atomicAdd(&g_cnt[edge_dst(ei, e)], 1);
        return;
    }

    // --- GEMM role ---
    for (int i = threadIdx.x; i < FIN * HID / 4; i += blockDim.x)
        Ws[i] = ((const ulonglong2*)W1)[i];
    __syncthreads();

    int row = blockIdx.x * blockDim.x + threadIdx.x;
    if (row >= NN) return;

    unsigned long long acc[HID / 2];
#pragma unroll
    for (int c = 0; c < HID / 2; c++) acc[c] = 0ULL;

    const float4* xr = (const float4*)(x + (size_t)row * FIN);
#pragma unroll 2
    for (int k4 = 0; k4 < FIN / 4; k4++) {
        float4 xv = __ldg(xr + k4);
        float xk[4] = {xv.x, xv.y, xv.z, xv.w};
#pragma unroll
        for (int kk = 0; kk < 4; kk++) {
            unsigned long long xs2 = pk2(xk[kk], xk[kk]);
            const ulonglong2* wr = &Ws[(k4 * 4 + kk) * (HID / 4)];
#pragma unroll
            for (int c4 = 0; c4 < HID / 4; c4++) {
                ulonglong2 w = wr[c4];
                fma2(acc[c4 * 2 + 0], xs2, w.x);
                fma2(acc[c4 * 2 + 1], xs2, w.y);
            }
        }
    }

    uint4* h1 = &g_hs1h[row * 8];
#pragma unroll
    for (int j = 0; j < 8; j++) {
        uint4 v;
        unsigned int* vp = (unsigned int*)&v;
#pragma unroll
        for (int q = 0; q < 4; q++) {
            float lo, hi;
            unpk2(acc[4 * j + q], lo, hi);
            __half2 h = __floats2half2_rn(lo, hi);
            vp[q] = *(unsigned int*)&h;
        }
        h1[j] = v;
    }
}

// ---------------------------------------------------------------------------
// Scan 1: warp-shuffle block scan of g_cnt -> partial inclusive in g_off[i+1],
// block totals in g_bsum. Also computes dinv (needs only cnt).
__global__ void k_scan1() {
    __shared__ int wsum[32];
    int i = blockIdx.x * SCAN_B + threadIdx.x;
    int lane = threadIdx.x & 31, wid = threadIdx.x >> 5;
    int cnt = (i < NN) ? g_cnt[i] : 0;
    if (i < NN) g_dinv[i] = rsqrtf((float)cnt + 1.0f);
    int s = cnt;
#pragma unroll
    for (int d = 1; d < 32; d <<= 1) {
        int t = __shfl_up_sync(0xFFFFFFFFu, s, d);
        if (lane >= d) s += t;
    }
    if (lane == 31) wsum[wid] = s;
    __syncthreads();
    if (wid == 0) {
        int w = wsum[lane];
#pragma unroll
        for (int d = 1; d < 32; d <<= 1) {
            int t = __shfl_up_sync(0xFFFFFFFFu, w, d);
            if (lane >= d) w += t;
        }
        wsum[lane] = w;
    }
    __syncthreads();
    if (wid > 0) s += wsum[wid - 1];
    if (threadIdx.x == SCAN_B - 1) g_bsum[blockIdx.x] = s;
    if (i < NN) g_off[i + 1] = s;
}

// Scan 2+3 fused: every block redundantly scans the 98 block sums (cheap),
// then finalizes its chunk's offsets + insert cursors.
__global__ void k_scan23() {
    __shared__ int bpre[NB + 1];   // exclusive prefix of block sums
    if (threadIdx.x == 0) {
        int acc = 0;
        for (int b = 0; b < NB; b++) { bpre[b] = acc; acc += g_bsum[b]; }
        bpre[NB] = acc;
    }
    __syncthreads();

    int i = blockIdx.x * SCAN_B + threadIdx.x;
    if (i >= NN) return;
    int boff = bpre[blockIdx.x];
    int cnt  = g_cnt[i];
    int incl = g_off[i + 1] + boff;
    g_off[i + 1] = incl;
    g_pos[i]     = incl - cnt;
    if (i == 0) g_off[0] = 0;
}

// ---------------------------------------------------------------------------
// FUSED: bucket src by dst (CSR) + scale hs1h in place by dinv[node].
// Both depend only on the scan chain + gemm1; they overlap in one launch
// (bucket = atomic-bound, scale = streaming-bound).
__global__ void k_bucket_scale(const void* __restrict__ ei) {
    if (blockIdx.x < BUCKET_BLOCKS) {
        int e = blockIdx.x * blockDim.x + threadIdx.x;
        if (e >= NE) return;
        int s = edge_src(ei, e);
        int d = edge_dst(ei, e);
        int p = atomicAdd(&g_pos[d], 1);
        g_esrc[p] = s;
        return;
    }
    // --- scale role: hs1h[t] *= dinv[node] ---
    int t = (blockIdx.x - BUCKET_BLOCKS) * blockDim.x + threadIdx.x;
    if (t >= NN * 8) return;
    float di = g_dinv[t >> 3];
    uint4 v = g_hs1h[t];
    unsigned int* vp = (unsigned int*)&v;
#pragma unroll
    for (int q = 0; q < 4; q++) {
        __half2 h = *(__half2*)&vp[q];
        float2 f = __half22float2(h);
        h = __floats2half2_rn(f.x * di, f.y * di);
        vp[q] = *(unsigned int*)&h;
    }
    g_hs1h[t] = v;
}

// ---------------------------------------------------------------------------
// Aggregation layer 1: acc1[d] = sum over {d} ∪ neigh of pre-scaled hs1.
// One thread per (node, 8-half group); fp32 accumulate; 2-way unroll for MLP.
__global__ void k_agg1() {
    int idx = blockIdx.x * blockDim.x + threadIdx.x;
    if (idx >= NN * 8) return;
    int d = idx >> 3, g = idx & 7;
    int beg = g_off[d], end = g_off[d + 1];

    float a[8];
    {
        uint4 v = g_hs1h[idx];  // self term (pre-scaled by dinv[d])
        const __half2* hp = (const __half2*)&v;
#pragma unroll
        for (int q = 0; q < 4; q++) {
            float2 f = __half22float2(hp[q]);
            a[2 * q] = f.x; a[2 * q + 1] = f.y;
        }
    }
    int j = beg;
    for (; j + 1 < end; j += 2) {
        int s0 = __ldg(&g_esrc[j]);
        int s1 = __ldg(&g_esrc[j + 1]);
        uint4 v0 = __ldg(&g_hs1h[s0 * 8 + g]);
        uint4 v1 = __ldg(&g_hs1h[s1 * 8 + g]);
        const __half2* h0 = (const __half2*)&v0;
        const __half2* h1 = (const __half2*)&v1;
#pragma unroll
        for (int q = 0; q < 4; q++) {
            float2 f0 = __half22float2(h0[q]);
            float2 f1 = __half22float2(h1[q]);
            a[2 * q]     += f0.x + f1.x;
            a[2 * q + 1] += f0.y + f1.y;
        }
    }
    if (j < end) {
        int s0 = __ldg(&g_esrc[j]);
        uint4 v0 = __ldg(&g_hs1h[s0 * 8 + g]);
        const __half2* h0 = (const __half2*)&v0;
#pragma unroll
        for (int q = 0; q < 4; q++) {
            float2 f0 = __half22float2(h0[q]);
            a[2 * q] += f0.x; a[2 * q + 1] += f0.y;
        }
    }
    float4* o = (float4*)(g_acc1 + (size_t)d * HID + g * 8);
    o[0] = make_float4(a[0], a[1], a[2], a[3]);
    o[1] = make_float4(a[4], a[5], a[6], a[7]);
}

// ---------------------------------------------------------------------------
// GEMM2: in = relu(acc1[row]*dinv + b1); hs2 = (in @ W2) * dinv[row] as fp16.
__global__ void k_gemm2(const float* __restrict__ W2, const float* __restrict__ b1) {
    __shared__ ulonglong2 Ws[HID * NCLS / 4];  // 640 entries = 10KB
    __shared__ float b1s[HID];
    for (int i = threadIdx.x; i < HID * NCLS / 4; i += blockDim.x)
        Ws[i] = ((const ulonglong2*)W2)[i];
    for (int i = threadIdx.x; i < HID; i += blockDim.x) b1s[i] = b1[i];
    __syncthreads();

    int row = blockIdx.x * blockDim.x + threadIdx.x;
    if (row >= NN) return;

    float di = g_dinv[row];
    unsigned long long acc[NCLS / 2];
#pragma unroll
    for (int c = 0; c < NCLS / 2; c++) acc[c] = 0ULL;

    const float4* ar = (const float4*)(g_acc1 + (size_t)row * HID);
#pragma unroll 2
    for (int k4 = 0; k4 < HID / 4; k4++) {
        float4 av = ar[k4];
        float ak[4] = {av.x, av.y, av.z, av.w};
#pragma unroll
        for (int kk = 0; kk < 4; kk++) {
            int k = k4 * 4 + kk;
            float xv = fmaxf(ak[kk] * di + b1s[k], 0.0f);
            unsigned long long xs2 = pk2(xv, xv);
            const ulonglong2* wr = &Ws[k * (NCLS / 4)];
#pragma unroll
            for (int c4 = 0; c4 < NCLS / 4; c4++) {
                ulonglong2 w = wr[c4];
                fma2(acc[c4 * 2 + 0], xs2, w.x);
                fma2(acc[c4 * 2 + 1], xs2, w.y);
            }
        }
    }

    uint4* h2 = &g_hs2h[row * 5];
#pragma unroll
    for (int j = 0; j < 5; j++) {
        uint4 v;
        unsigned int* vp = (unsigned int*)&v;
#pragma unroll
        for (int q = 0; q < 4; q++) {
            float lo, hi;
            unpk2(acc[4 * j + q], lo, hi);
            __half2 h = __floats2half2_rn(lo * di, hi * di);
            vp[q] = *(unsigned int*)&h;
        }
        h2[j] = v;
    }
}

// ---------------------------------------------------------------------------
// Aggregation layer 2 + epilogue: out[d] = (hs2[d] + sum hs2[neigh])*dinv + b2.
__global__ void k_agg2(const float* __restrict__ b2, float* __restrict__ out) {
    int idx = blockIdx.x * blockDim.x + threadIdx.x;
    if (idx >= NN * 5) return;
    int d = idx / 5, g = idx - d * 5;
    int beg = g_off[d], end = g_off[d + 1];

    float a[8];
    {
        uint4 v = g_hs2h[idx];  // self term (idx == d*5+g)
        const __half2* hp = (const __half2*)&v;
#pragma unroll
        for (int q = 0; q < 4; q++) {
            float2 f = __half22float2(hp[q]);
            a[2 * q] = f.x; a[2 * q + 1] = f.y;
        }
    }
    int j = beg;
    for (; j + 1 < end; j += 2) {
        int s0 = __ldg(&g_esrc[j]);
        int s1 = __ldg(&g_esrc[j + 1]);
        uint4 v0 = __ldg(&g_hs2h[s0 * 5 + g]);
        uint4 v1 = __ldg(&g_hs2h[s1 * 5 + g]);
        const __half2* h0 = (const __half2*)&v0;
        const __half2* h1 = (const __half2*)&v1;
#pragma unroll
        for (int q = 0; q < 4; q++) {
            float2 f0 = __half22float2(h0[q]);
            float2 f1 = __half22float2(h1[q]);
            a[2 * q]     += f0.x + f1.x;
            a[2 * q + 1] += f0.y + f1.y;
        }
    }
    if (j < end) {
        int s0 = __ldg(&g_esrc[j]);
        uint4 v0 = __ldg(&g_hs2h[s0 * 5 + g]);
        const __half2* h0 = (const __half2*)&v0;
#pragma unroll
        for (int q = 0; q < 4; q++) {
            float2 f0 = __half22float2(h0[q]);
            a[2 * q] += f0.x; a[2 * q + 1] += f0.y;
        }
    }
    float di = g_dinv[d];
    const float4* bp = (const float4*)(b2 + g * 8);
    float4 b0 = __ldg(bp), b1v = __ldg(bp + 1);
    float4* o = (float4*)(out + (size_t)d * NCLS + g * 8);
    o[0] = make_float4(a[0] * di + b0.x, a[1] * di + b0.y,
                       a[2] * di + b0.z, a[3] * di + b0.w);
    o[1] = make_float4(a[4] * di + b1v.x, a[5] * di + b1v.y,
                       a[6] * di + b1v.z, a[7] * di + b1v.w);
}

// ---------------------------------------------------------------------------
extern "C" void kernel_launch(void* const* d_in, const int* in_sizes, int n_in,
                              void* d_out, int out_size) {
    const float* x   = (const float*)d_in[0];
    const void*  ei  = d_in[1];                 // [2, NE], int32 OR int64
    const float* W1  = (const float*)d_in[2];
    const float* b1  = (const float*)d_in[3];
    const float* W2  = (const float*)d_in[4];
    const float* b2  = (const float*)d_in[5];
    float*       out = (float*)d_out;

    // init (dtype detect + zero counts)
    k_init<<<(NN + 255) / 256, 256>>>(ei);

    // GEMM1 (unscaled) overlapped with degree count in one launch
    k_gemm1_cnt<<<GEMM1_BLOCKS + CNT_BLOCKS, 128>>>(x, W1, ei);

    // CSR scan (2 launches) — dinv computed in scan1
    k_scan1<<<NB, SCAN_B>>>();
    k_scan23<<<NB, SCAN_B>>>();

    // bucket (CSR fill) overlapped with hs1 *= dinv scaling
    k_bucket_scale<<<BUCKET_BLOCKS + SCALE_BLOCKS, 256>>>(ei);

    // layer 1 aggregate (pure gather of pre-scaled fp16 rows)
    k_agg1<<<(NN * 8 + 255) / 256, 256>>>();

    // layer 2 (relu fused into GEMM2 input; dinv+b2 fused into agg2)
    k_gemm2<<<(NN + 127) / 128, 128>>>(W2, b1);
    k_agg2<<<(NN * 5 + 319) / 320, 320>>>(b2, out);
}

// round 10
// speedup vs baseline: 1.0777x; 1.0777x over previous
#include <cuda_runtime.h>
#include <cuda_fp16.h>
#include <cuda_bf16.h>

// Problem constants (match reference)
#define NN   100000      // nodes
#define FIN  128         // input features
#define HID  64          // hidden
#define NCLS 40          // classes
#define NE   1600000     // edges

#define SCAN_B 1024
#define NB ((NN + SCAN_B - 1) / SCAN_B)   // 98
#define GEMM1_BLOCKS ((NN + 127) / 128)   // 782
#define BUK_BLOCKS 254                    // fits wave-1 residual next to gemm blocks

// Scratch (device globals — no allocation allowed)
__device__ int   g_is64;
__device__ int   g_cnt [NN];
__device__ int   g_off [NN + 1];
__device__ int   g_pos [NN];
__device__ int   g_bsum[NB];
__device__ int   g_esrc[NE];          // src indices bucketed by dst (CSR)
__device__ float g_dinv[NN];
__device__ uint4 g_hs1h[NN * 8];      // (x@W1)*dinv fp16: 64 halfs/row
__device__ uint4 g_acc1h[NN * 8];     // layer-1 aggregate, fp16
__device__ uint4 g_hs2h[NN * 5];      // (relu@W2)*dinv fp16: 40 halfs/row

// ---------------------------------------------------------------------------
// Packed f32x2 helpers (Blackwell FFMA2 — only reachable via PTX)
__device__ __forceinline__ unsigned long long pk2(float lo, float hi) {
    unsigned long long r;
    asm("mov.b64 %0, {%1, %2};" : "=l"(r) : "f"(lo), "f"(hi));
    return r;
}
__device__ __forceinline__ void fma2(unsigned long long& d,
                                     unsigned long long a, unsigned long long b) {
    asm("fma.rn.f32x2 %0, %1, %2, %0;" : "+l"(d) : "l"(a), "l"(b));
}
__device__ __forceinline__ void unpk2(unsigned long long v, float& x, float& y) {
    asm("mov.b64 {%0, %1}, %2;" : "=f"(x), "=f"(y) : "l"(v));
}

// ---------------------------------------------------------------------------
// Edge-index dtype detection (JAX silently downcasts int64 -> int32 by default)
__device__ __forceinline__ int edge_src(const void* __restrict__ ei, int e) {
    if (g_is64) return (int)((const long long*)ei)[e];
    return ((const int*)ei)[e];
}
__device__ __forceinline__ int edge_dst(const void* __restrict__ ei, int e) {
    if (g_is64) return (int)((const long long*)ei)[NE + e];
    return ((const int*)ei)[NE + e];
}

// Fused: detect dtype (block 0, thread 0) + zero g_cnt (all threads)
__global__ void k_init(const void* __restrict__ ei) {
    if (blockIdx.x == 0 && threadIdx.x == 0) {
        const unsigned long long* p = (const unsigned long long*)ei;
        int is64 = 1;
        for (int i = 0; i < 2048; i++) {
            if (p[i] >= (unsigned long long)NN) { is64 = 0; break; }
        }
        g_is64 = is64;
    }
    int i = blockIdx.x * blockDim.x + threadIdx.x;
    if (i < NN) g_cnt[i] = 0;
}

// Degree count (runs first; gemm1 no longer blocks on it)
__global__ void k_cnt(const void* __restrict__ ei) {
    int e = blockIdx.x * blockDim.x + threadIdx.x;
    if (e < NE) atomicAdd(&g_cnt[edge_dst(ei, e)], 1);
}

// ---------------------------------------------------------------------------
// Scan 1: warp-shuffle block scan of g_cnt -> partial inclusive in g_off[i+1],
// block totals in g_bsum. Also computes dinv.
__global__ void k_scan1() {
    __shared__ int wsum[32];
    int i = blockIdx.x * SCAN_B + threadIdx.x;
    int lane = threadIdx.x & 31, wid = threadIdx.x >> 5;
    int cnt = (i < NN) ? g_cnt[i] : 0;
    if (i < NN) g_dinv[i] = rsqrtf((float)cnt + 1.0f);
    int s = cnt;
#pragma unroll
    for (int d = 1; d < 32; d <<= 1) {
        int t = __shfl_up_sync(0xFFFFFFFFu, s, d);
        if (lane >= d) s += t;
    }
    if (lane == 31) wsum[wid] = s;
    __syncthreads();
    if (wid == 0) {
        int w = wsum[lane];
#pragma unroll
        for (int d = 1; d < 32; d <<= 1) {
            int t = __shfl_up_sync(0xFFFFFFFFu, w, d);
            if (lane >= d) w += t;
        }
        wsum[lane] = w;
    }
    __syncthreads();
    if (wid > 0) s += wsum[wid - 1];
    if (threadIdx.x == SCAN_B - 1) g_bsum[blockIdx.x] = s;
    if (i < NN) g_off[i + 1] = s;
}

// Scan 2+3 fused: parallel shuffle scan of the NB block sums (first 128
// threads), then finalize offsets + insert cursors for this block's chunk.
__global__ void k_scan23() {
    __shared__ int bpre[128];   // exclusive prefix of block sums
    __shared__ int wsum[4];
    int t = threadIdx.x, lane = t & 31, w4 = (t >> 5) & 3;
    int v = 0, s = 0;
    if (t < 128) {
        v = (t < NB) ? g_bsum[t] : 0;
        s = v;
#pragma unroll
        for (int d = 1; d < 32; d <<= 1) {
            int u = __shfl_up_sync(0xFFFFFFFFu, s, d);
            if (lane >= d) s += u;
        }
        if (lane == 31) wsum[w4] = s;
    }
    __syncthreads();
    if (t == 0) {
        int acc = 0;
#pragma unroll
        for (int w = 0; w < 4; w++) { int q = wsum[w]; wsum[w] = acc; acc += q; }
    }
    __syncthreads();
    if (t < 128) bpre[t] = s + wsum[w4] - v;   // exclusive prefix
    __syncthreads();

    int i = blockIdx.x * SCAN_B + threadIdx.x;
    if (i >= NN) return;
    int boff = bpre[blockIdx.x];
    int cnt  = g_cnt[i];
    int incl = g_off[i + 1] + boff;
    g_off[i + 1] = incl;
    g_pos[i]     = incl - cnt;
    if (i == 0) g_off[0] = 0;
}

// ---------------------------------------------------------------------------
// FUSED: bucket role (blocks [0, BUK_BLOCKS), grid-stride over edges) runs in
// wave 1 alongside GEMM1 blocks. GEMM1 writes (x@W1)*dinv[row] as fp16 —
// dinv is already available, so no separate scale pass and no per-edge
// dinv gather later.
__global__ void k_gemm1_bucket(const float* __restrict__ x,
                               const float* __restrict__ W1,
                               const void* __restrict__ ei) {
    __shared__ ulonglong2 Ws[FIN * HID / 4];  // 2048 entries = 32KB

    if (blockIdx.x < BUK_BLOCKS) {
        // --- bucket role: CSR fill (atomic-bound) ---
        int t = blockIdx.x * blockDim.x + threadIdx.x;
        int stride = BUK_BLOCKS * blockDim.x;
        for (int e = t; e < NE; e += stride) {
            int s = edge_src(ei, e);
            int d = edge_dst(ei, e);
            int p = atomicAdd(&g_pos[d], 1);
            g_esrc[p] = s;
        }
        return;
    }

    // --- GEMM role (FMA-bound) ---
    for (int i = threadIdx.x; i < FIN * HID / 4; i += blockDim.x)
        Ws[i] = ((const ulonglong2*)W1)[i];
    __syncthreads();

    int row = (blockIdx.x - BUK_BLOCKS) * blockDim.x + threadIdx.x;
    if (row >= NN) return;

    unsigned long long acc[HID / 2];
#pragma unroll
    for (int c = 0; c < HID / 2; c++) acc[c] = 0ULL;

    const float4* xr = (const float4*)(x + (size_t)row * FIN);
#pragma unroll 2
    for (int k4 = 0; k4 < FIN / 4; k4++) {
        float4 xv = __ldg(xr + k4);
        float xk[4] = {xv.x, xv.y, xv.z, xv.w};
#pragma unroll
        for (int kk = 0; kk < 4; kk++) {
            unsigned long long xs2 = pk2(xk[kk], xk[kk]);
            const ulonglong2* wr = &Ws[(k4 * 4 + kk) * (HID / 4)];
#pragma unroll
            for (int c4 = 0; c4 < HID / 4; c4++) {
                ulonglong2 w = wr[c4];
                fma2(acc[c4 * 2 + 0], xs2, w.x);
                fma2(acc[c4 * 2 + 1], xs2, w.y);
            }
        }
    }

    float di = g_dinv[row];
    uint4* h1 = &g_hs1h[row * 8];
#pragma unroll
    for (int j = 0; j < 8; j++) {
        uint4 v;
        unsigned int* vp = (unsigned int*)&v;
#pragma unroll
        for (int q = 0; q < 4; q++) {
            float lo, hi;
            unpk2(acc[4 * j + q], lo, hi);
            __half2 h = __floats2half2_rn(lo * di, hi * di);
            vp[q] = *(unsigned int*)&h;
        }
        h1[j] = v;
    }
}

// ---------------------------------------------------------------------------
// Aggregation layer 1: acc1[d] = sum over {d} ∪ neigh of pre-scaled hs1.
// One thread per (node, 8-half group); fp32 accumulate; fp16 output.
__global__ void k_agg1() {
    int idx = blockIdx.x * blockDim.x + threadIdx.x;
    if (idx >= NN * 8) return;
    int d = idx >> 3, g = idx & 7;
    int beg = g_off[d], end = g_off[d + 1];

    float a[8];
    {
        uint4 v = g_hs1h[idx];  // self term (pre-scaled by dinv[d])
        const __half2* hp = (const __half2*)&v;
#pragma unroll
        for (int q = 0; q < 4; q++) {
            float2 f = __half22float2(hp[q]);
            a[2 * q] = f.x; a[2 * q + 1] = f.y;
        }
    }
    int j = beg;
    for (; j + 1 < end; j += 2) {
        int s0 = __ldg(&g_esrc[j]);
        int s1 = __ldg(&g_esrc[j + 1]);
        uint4 v0 = __ldg(&g_hs1h[s0 * 8 + g]);
        uint4 v1 = __ldg(&g_hs1h[s1 * 8 + g]);
        const __half2* h0 = (const __half2*)&v0;
        const __half2* h1 = (const __half2*)&v1;
#pragma unroll
        for (int q = 0; q < 4; q++) {
            float2 f0 = __half22float2(h0[q]);
            float2 f1 = __half22float2(h1[q]);
            a[2 * q]     += f0.x + f1.x;
            a[2 * q + 1] += f0.y + f1.y;
        }
    }
    if (j < end) {
        int s0 = __ldg(&g_esrc[j]);
        uint4 v0 = __ldg(&g_hs1h[s0 * 8 + g]);
        const __half2* h0 = (const __half2*)&v0;
#pragma unroll
        for (int q = 0; q < 4; q++) {
            float2 f0 = __half22float2(h0[q]);
            a[2 * q] += f0.x; a[2 * q + 1] += f0.y;
        }
    }
    uint4 o;
    unsigned int* op = (unsigned int*)&o;
#pragma unroll
    for (int q = 0; q < 4; q++) {
        __half2 h = __floats2half2_rn(a[2 * q], a[2 * q + 1]);
        op[q] = *(unsigned int*)&h;
    }
    g_acc1h[idx] = o;
}

// ---------------------------------------------------------------------------
// GEMM2: in = relu(acc1[row]*dinv + b1); hs2 = (in @ W2) * dinv[row] as fp16.
__global__ void k_gemm2(const float* __restrict__ W2, const float* __restrict__ b1) {
    __shared__ ulonglong2 Ws[HID * NCLS / 4];  // 640 entries = 10KB
    __shared__ float b1s[HID];
    for (int i = threadIdx.x; i < HID * NCLS / 4; i += blockDim.x)
        Ws[i] = ((const ulonglong2*)W2)[i];
    for (int i = threadIdx.x; i < HID; i += blockDim.x) b1s[i] = b1[i];
    __syncthreads();

    int row = blockIdx.x * blockDim.x + threadIdx.x;
    if (row >= NN) return;

    float di = g_dinv[row];
    unsigned long long acc[NCLS / 2];
#pragma unroll
    for (int c = 0; c < NCLS / 2; c++) acc[c] = 0ULL;

    const uint4* ar = &g_acc1h[row * 8];
#pragma unroll
    for (int j = 0; j < 8; j++) {
        uint4 v = ar[j];
        const __half2* hp = (const __half2*)&v;
        float ak[8];
#pragma unroll
        for (int q = 0; q < 4; q++) {
            float2 f = __half22float2(hp[q]);
            ak[2 * q] = f.x; ak[2 * q + 1] = f.y;
        }
#pragma unroll
        for (int kk = 0; kk < 8; kk++) {
            int k = j * 8 + kk;
            float xv = fmaxf(ak[kk] * di + b1s[k], 0.0f);
            unsigned long long xs2 = pk2(xv, xv);
            const ulonglong2* wr = &Ws[k * (NCLS / 4)];
#pragma unroll
            for (int c4 = 0; c4 < NCLS / 4; c4++) {
                ulonglong2 w = wr[c4];
                fma2(acc[c4 * 2 + 0], xs2, w.x);
                fma2(acc[c4 * 2 + 1], xs2, w.y);
            }
        }
    }

    uint4* h2 = &g_hs2h[row * 5];
#pragma unroll
    for (int j = 0; j < 5; j++) {
        uint4 v;
        unsigned int* vp = (unsigned int*)&v;
#pragma unroll
        for (int q = 0; q < 4; q++) {
            float lo, hi;
            unpk2(acc[4 * j + q], lo, hi);
            __half2 h = __floats2half2_rn(lo * di, hi * di);
            vp[q] = *(unsigned int*)&h;
        }
        h2[j] = v;
    }
}

// ---------------------------------------------------------------------------
// Aggregation layer 2 + epilogue: out[d] = (hs2[d] + sum hs2[neigh])*dinv + b2.
__global__ void k_agg2(const float* __restrict__ b2, float* __restrict__ out) {
    int idx = blockIdx.x * blockDim.x + threadIdx.x;
    if (idx >= NN * 5) return;
    int d = idx / 5, g = idx - d * 5;
    int beg = g_off[d], end = g_off[d + 1];

    float a[8];
    {
        uint4 v = g_hs2h[idx];  // self term (idx == d*5+g)
        const __half2* hp = (const __half2*)&v;
#pragma unroll
        for (int q = 0; q < 4; q++) {
            float2 f = __half22float2(hp[q]);
            a[2 * q] = f.x; a[2 * q + 1] = f.y;
        }
    }
    int j = beg;
    for (; j + 1 < end; j += 2) {
        int s0 = __ldg(&g_esrc[j]);
        int s1 = __ldg(&g_esrc[j + 1]);
        uint4 v0 = __ldg(&g_hs2h[s0 * 5 + g]);
        uint4 v1 = __ldg(&g_hs2h[s1 * 5 + g]);
        const __half2* h0 = (const __half2*)&v0;
        const __half2* h1 = (const __half2*)&v1;
#pragma unroll
        for (int q = 0; q < 4; q++) {
            float2 f0 = __half22float2(h0[q]);
            float2 f1 = __half22float2(h1[q]);
            a[2 * q]     += f0.x + f1.x;
            a[2 * q + 1] += f0.y + f1.y;
        }
    }
    if (j < end) {
        int s0 = __ldg(&g_esrc[j]);
        uint4 v0 = __ldg(&g_hs2h[s0 * 5 + g]);
        const __half2* h0 = (const __half2*)&v0;
#pragma unroll
        for (int q = 0; q < 4; q++) {
            float2 f0 = __half22float2(h0[q]);
            a[2 * q] += f0.x; a[2 * q + 1] += f0.y;
        }
    }
    float di = g_dinv[d];
    const float4* bp = (const float4*)(b2 + g * 8);
    float4 b0 = __ldg(bp), b1v = __ldg(bp + 1);
    float4* o = (float4*)(out + (size_t)d * NCLS + g * 8);
    o[0] = make_float4(a[0] * di + b0.x, a[1] * di + b0.y,
                       a[2] * di + b0.z, a[3] * di + b0.w);
    o[1] = make_float4(a[4] * di + b1v.x, a[5] * di + b1v.y,
                       a[6] * di + b1v.z, a[7] * di + b1v.w);
}

// ---------------------------------------------------------------------------
extern "C" void kernel_launch(void* const* d_in, const int* in_sizes, int n_in,
                              void* d_out, int out_size) {
    const float* x   = (const float*)d_in[0];
    const void*  ei  = d_in[1];                 // [2, NE], int32 OR int64
    const float* W1  = (const float*)d_in[2];
    const float* b1  = (const float*)d_in[3];
    const float* W2  = (const float*)d_in[4];
    const float* b2  = (const float*)d_in[5];
    float*       out = (float*)d_out;

    // init (dtype detect + zero counts), degree count, scans (+dinv)
    k_init<<<(NN + 255) / 256, 256>>>(ei);
    k_cnt<<<(NE + 255) / 256, 256>>>(ei);
    k_scan1<<<NB, SCAN_B>>>();
    k_scan23<<<NB, SCAN_B>>>();

    // CSR bucket fill overlapped with GEMM1 (writes pre-scaled fp16 hs1)
    k_gemm1_bucket<<<BUK_BLOCKS + GEMM1_BLOCKS, 128>>>(x, W1, ei);

    // layer 1 aggregate (pure gather, fp16 in/out, fp32 accumulate)
    k_agg1<<<(NN * 8 + 255) / 256, 256>>>();

    // layer 2 (relu fused into GEMM2 input; dinv+b2 fused into agg2)
    k_gemm2<<<(NN + 127) / 128, 128>>>(W2, b1);
    k_agg2<<<(NN * 5 + 319) / 320, 320>>>(b2, out);
}